// round 11
// baseline (speedup 1.0000x reference)
#include <cuda_runtime.h>

#define N_NODES 100000
#define E_EDGES 1600000
#define FIN  16
#define FMID 32
#define FOUT 16
#define CAP  64                            // padded per-node capacity (mean deg 16)

// ---------------- device scratch ----------------
__device__ int   g_cnt[N_NODES];           // arrival counter / degree (0 at replay start)
__device__ int   g_degc[N_NODES];          // min(deg, CAP) snapshot for gathers
__device__ float g_dinv[N_NODES];
__device__ int   g_psrow[N_NODES * CAP];   // padded adjacency (rows by target)
__device__ int   g_spill_r[E_EDGES];       // overflow edges (rank >= CAP)
__device__ int   g_spill_c[E_EDGES];
__device__ int   g_spill_cursor;           // 0 at replay start
__device__ int   g_spill_n;                // snapshot for gathers
__device__ float g_h1s[N_NODES * FMID];    // (x @ W1) * dinv
__device__ float g_h2s[N_NODES * FOUT];    // (relu(o1) @ W2) * dinv

__device__ __forceinline__ void add4(float4& a, const float4 b) {
    a.x += b.x; a.y += b.y; a.z += b.z; a.w += b.w;
}
__device__ __forceinline__ void shfl_xor_add4(float4& a, int m) {
    a.x += __shfl_xor_sync(0xffffffffu, a.x, m);
    a.y += __shfl_xor_sync(0xffffffffu, a.y, m);
    a.z += __shfl_xor_sync(0xffffffffu, a.z, m);
    a.w += __shfl_xor_sync(0xffffffffu, a.w, m);
}

// ---------------- kernels ----------------

// Fused dtype-detect + padded-CSR build. One atomic per edge gives both the
// degree histogram AND the final storage slot (no scan, no place pass).
__global__ void k_build(const unsigned int* __restrict__ words,
                        const void* __restrict__ edge_raw, int E) {
    __shared__ unsigned int s_or;
    if (threadIdx.x == 0) s_or = 0u;
    __syncthreads();
    unsigned int acc = words[2 * threadIdx.x + 1] | words[2 * (threadIdx.x + 256) + 1];
    #pragma unroll
    for (int s = 16; s > 0; s >>= 1)
        acc |= __shfl_xor_sync(0xffffffffu, acc, s);
    if ((threadIdx.x & 31) == 0) atomicOr(&s_or, acc);
    __syncthreads();
    const int is64 = (s_or == 0u) ? 1 : 0;

    int base = (blockIdx.x * blockDim.x + threadIdx.x) * 4;
    if (base >= E) return;
    int n = min(4, E - base);

    int r[4], c[4];
    if (is64) {
        const long long* p = (const long long*)edge_raw;
        #pragma unroll
        for (int k = 0; k < 4; k++) if (k < n) {
            r[k] = (int)p[base + k];
            c[k] = (int)p[E + base + k];
        }
    } else {
        const int* p = (const int*)edge_raw;
        #pragma unroll
        for (int k = 0; k < 4; k++) if (k < n) {
            r[k] = p[base + k];
            c[k] = p[E + base + k];
        }
    }
    int rank[4];
    #pragma unroll
    for (int k = 0; k < 4; k++) if (k < n)
        rank[k] = atomicAdd(&g_cnt[c[k]], 1);
    #pragma unroll
    for (int k = 0; k < 4; k++) if (k < n) {
        if (rank[k] < CAP) {
            g_psrow[c[k] * CAP + rank[k]] = r[k];
        } else {                                   // correctness fallback (empty here)
            int s = atomicAdd(&g_spill_cursor, 1);
            g_spill_c[s] = c[k];
            g_spill_r[s] = r[k];
        }
    }
}

// dinv + h1s = (x@W1)*dinv + counter snapshot/reset. Warp per node (32 lanes).
__global__ void k_lin1(const float* __restrict__ x,
                       const float* __restrict__ W1) {
    __shared__ float sW[FIN * FMID];
    for (int t = threadIdx.x; t < FIN * FMID; t += blockDim.x) sW[t] = W1[t];
    __syncthreads();
    int idx = blockIdx.x * blockDim.x + threadIdx.x;
    if (idx == 0) {
        g_spill_n = g_spill_cursor;
        g_spill_cursor = 0;
    }
    if (idx >= N_NODES * FMID) return;
    int i = idx >> 5;
    int f = idx & 31;
    int deg = g_cnt[i];
    float d = rsqrtf((float)(deg + 1));     // +1 self-loop
    __syncwarp();
    if (f == 0) {
        g_dinv[i] = d;
        g_degc[i] = min(deg, CAP);
        g_cnt[i]  = 0;
    }
    float acc = 0.0f;
    #pragma unroll
    for (int k = 0; k < FIN; k++)
        acc = fmaf(__ldg(&x[i * FIN + k]), sW[k * FMID + f], acc);
    g_h1s[idx] = acc * d;
}

// Fused gather1 + lin2. Full warp per node.
// lane = es*8 + q : es in 0..3 (edge slot), q in 0..7 (float4 quad of FMID=32).
__global__ void k_gather1_lin2(const float* __restrict__ W2,
                               const float* __restrict__ b1) {
    __shared__ float sW[FMID * FOUT];
    __shared__ float so1[8][FMID];              // 8 warps per 256-thread block
    for (int t = threadIdx.x; t < FMID * FOUT; t += blockDim.x) sW[t] = W2[t];
    __syncthreads();

    int w = (blockIdx.x * blockDim.x + threadIdx.x) >> 5;
    if (w >= N_NODES) return;
    int lane = threadIdx.x & 31;
    int q  = lane & 7;
    int es = lane >> 3;
    int wl = (threadIdx.x >> 5) & 7;

    const float4* h1s4 = (const float4*)g_h1s;  // node stride = 8 float4
    const int* adj = &g_psrow[w * CAP];
    int deg = g_degc[w];

    float4 acc = make_float4(0.f, 0.f, 0.f, 0.f);
    if (es == 0) acc = __ldg(&h1s4[w * 8 + q]); // self-loop
    for (int j = 0; j < deg; j += 8) {          // 8 edges in flight per iter
        int j0 = j + es, j1 = j + 4 + es;
        if (j0 < deg) {
            int r = __ldg(&adj[j0]);
            add4(acc, __ldg(&h1s4[r * 8 + q]));
        }
        if (j1 < deg) {
            int r = __ldg(&adj[j1]);
            add4(acc, __ldg(&h1s4[r * 8 + q]));
        }
    }
    int sn = g_spill_n;                         // 0 for this input
    for (int i = 0; i < sn; i++)
        if (es == 0 && g_spill_c[i] == w)
            add4(acc, __ldg(&h1s4[g_spill_r[i] * 8 + q]));

    shfl_xor_add4(acc, 8);
    shfl_xor_add4(acc, 16);                     // lanes 0..7 hold u1 quad q

    float d = g_dinv[w];
    if (lane < 8) {
        float4 bq = __ldg(&((const float4*)b1)[q]);
        float4 o;
        o.x = fmaxf(fmaf(acc.x, d, bq.x), 0.f);
        o.y = fmaxf(fmaf(acc.y, d, bq.y), 0.f);
        o.z = fmaxf(fmaf(acc.z, d, bq.z), 0.f);
        o.w = fmaxf(fmaf(acc.w, d, bq.w), 0.f);
        ((float4*)so1[wl])[q] = o;
    }
    __syncwarp();
    if (lane < FOUT) {
        float s = 0.0f;
        #pragma unroll
        for (int k = 0; k < FMID; k++)
            s = fmaf(so1[wl][k], sW[k * FOUT + lane], s);
        g_h2s[w * FOUT + lane] = s * d;
    }
}

// Fused gather2 + final. Full warp per node.
// lane = es*4 + q : es in 0..7 (edge slot), q in 0..3 (float4 quad of FOUT=16).
__global__ void k_gather2_final(const float* __restrict__ fcW,
                                const float* __restrict__ fcb,
                                const float* __restrict__ b2,
                                float* __restrict__ out) {
    int w = (blockIdx.x * blockDim.x + threadIdx.x) >> 5;
    if (w >= N_NODES) return;
    int lane = threadIdx.x & 31;
    int q  = lane & 3;
    int es = lane >> 2;

    const float4* h2s4 = (const float4*)g_h2s;  // node stride = 4 float4
    const int* adj = &g_psrow[w * CAP];
    int deg = g_degc[w];

    float4 acc = make_float4(0.f, 0.f, 0.f, 0.f);
    if (es == 0) acc = __ldg(&h2s4[w * 4 + q]); // self-loop
    for (int j = 0; j < deg; j += 16) {         // 16 edges in flight per iter
        int j0 = j + es, j1 = j + 8 + es;
        if (j0 < deg) {
            int r = __ldg(&adj[j0]);
            add4(acc, __ldg(&h2s4[r * 4 + q]));
        }
        if (j1 < deg) {
            int r = __ldg(&adj[j1]);
            add4(acc, __ldg(&h2s4[r * 4 + q]));
        }
    }
    int sn = g_spill_n;
    for (int i = 0; i < sn; i++)
        if (es == 0 && g_spill_c[i] == w)
            add4(acc, __ldg(&h2s4[g_spill_r[i] * 4 + q]));

    shfl_xor_add4(acc, 4);
    shfl_xor_add4(acc, 8);
    shfl_xor_add4(acc, 16);                     // lanes 0..3 hold u2 quad q

    if (lane < 4) {
        float d = g_dinv[w];
        float4 bq = __ldg(&((const float4*)b2)[q]);
        float4 wq = __ldg(&((const float4*)fcW)[q]);
        float s = fmaxf(fmaf(acc.x, d, bq.x), 0.f) * wq.x
                + fmaxf(fmaf(acc.y, d, bq.y), 0.f) * wq.y
                + fmaxf(fmaf(acc.z, d, bq.z), 0.f) * wq.z
                + fmaxf(fmaf(acc.w, d, bq.w), 0.f) * wq.w;
        s += __shfl_xor_sync(0x0000000fu, s, 1, 4);
        s += __shfl_xor_sync(0x0000000fu, s, 2, 4);
        if (lane == 0) out[w] = s + __ldg(&fcb[0]);
    }
}

// ---------------- launch ----------------
extern "C" void kernel_launch(void* const* d_in, const int* in_sizes, int n_in,
                              void* d_out, int out_size) {
    const void*  edge = d_in[0];
    const float* x    = (const float*)d_in[1];
    const float* W1   = (const float*)d_in[2];
    const float* b1   = (const float*)d_in[3];
    const float* W2   = (const float*)d_in[4];
    const float* b2   = (const float*)d_in[5];
    const float* fcW  = (const float*)d_in[6];
    const float* fcb  = (const float*)d_in[7];
    float* out = (float*)d_out;

    const int E = in_sizes[0] / 2;
    const int T = 256;

    k_build        <<<(E / 4 + T - 1) / T, T>>>((const unsigned int*)edge, edge, E);
    k_lin1         <<<(N_NODES * 32 + T - 1) / T, T>>>(x, W1);
    k_gather1_lin2 <<<(N_NODES * 32 + T - 1) / T, T>>>(W2, b1);
    k_gather2_final<<<(N_NODES * 32 + T - 1) / T, T>>>(fcW, fcb, b2, out);
}

// round 12
// speedup vs baseline: 1.2433x; 1.2433x over previous
#include <cuda_runtime.h>

#define N_NODES 100000
#define E_EDGES 1600000
#define FIN  16
#define FMID 32
#define FOUT 16
#define CAP  64                            // padded per-node capacity (mean deg 16)

// ---------------- device scratch ----------------
__device__ int   g_cnt[N_NODES];           // arrival counter / degree (0 at replay start)
__device__ int   g_degc[N_NODES];          // min(deg, CAP) snapshot for gathers
__device__ float g_dinv[N_NODES];
__device__ int   g_psrow[N_NODES * CAP];   // padded adjacency (rows by target)
__device__ int   g_spill_r[E_EDGES];       // overflow edges (rank >= CAP)
__device__ int   g_spill_c[E_EDGES];
__device__ int   g_spill_cursor;           // 0 at replay start
__device__ int   g_spill_n;                // snapshot for gathers
__device__ float g_xs [N_NODES * FIN];     // x * dinv  (layer-1 gather source, 64B rows)
__device__ float g_h2s[N_NODES * FOUT];    // (relu(o1) @ W2) * dinv

// ---------------- kernels ----------------

// Fused dtype-detect + padded-CSR build. One atomic per edge gives both the
// degree histogram AND the final storage slot (no scan, no place pass).
__global__ void k_build(const unsigned int* __restrict__ words,
                        const void* __restrict__ edge_raw, int E) {
    __shared__ unsigned int s_or;
    if (threadIdx.x == 0) s_or = 0u;
    __syncthreads();
    unsigned int acc = words[2 * threadIdx.x + 1] | words[2 * (threadIdx.x + 256) + 1];
    #pragma unroll
    for (int s = 16; s > 0; s >>= 1)
        acc |= __shfl_xor_sync(0xffffffffu, acc, s);
    if ((threadIdx.x & 31) == 0) atomicOr(&s_or, acc);
    __syncthreads();
    const int is64 = (s_or == 0u) ? 1 : 0;

    int base = (blockIdx.x * blockDim.x + threadIdx.x) * 4;
    if (base >= E) return;
    int n = min(4, E - base);

    int r[4], c[4];
    if (is64) {
        const long long* p = (const long long*)edge_raw;
        #pragma unroll
        for (int k = 0; k < 4; k++) if (k < n) {
            r[k] = (int)p[base + k];
            c[k] = (int)p[E + base + k];
        }
    } else {
        const int* p = (const int*)edge_raw;
        #pragma unroll
        for (int k = 0; k < 4; k++) if (k < n) {
            r[k] = p[base + k];
            c[k] = p[E + base + k];
        }
    }
    int rank[4];
    #pragma unroll
    for (int k = 0; k < 4; k++) if (k < n)
        rank[k] = atomicAdd(&g_cnt[c[k]], 1);
    #pragma unroll
    for (int k = 0; k < 4; k++) if (k < n) {
        if (rank[k] < CAP) {
            g_psrow[c[k] * CAP + rank[k]] = r[k];
        } else {                                   // correctness fallback (empty here)
            int s = atomicAdd(&g_spill_cursor, 1);
            g_spill_c[s] = c[k];
            g_spill_r[s] = r[k];
        }
    }
}

// xs = x * dinv ; degree snapshot + counter reset. Half-warp per node (16 lanes).
__global__ void k_scale(const float* __restrict__ x) {
    int idx = blockIdx.x * blockDim.x + threadIdx.x;
    if (idx == 0) {
        g_spill_n = g_spill_cursor;
        g_spill_cursor = 0;
    }
    if (idx >= N_NODES * FIN) return;
    int i = idx >> 4;
    int f = idx & 15;
    int deg = g_cnt[i];                     // all 16 lanes read before lane-0 resets
    float d = rsqrtf((float)(deg + 1));     // +1 self-loop
    __syncwarp();
    if (f == 0) {
        g_dinv[i] = d;
        g_degc[i] = min(deg, CAP);
        g_cnt[i]  = 0;                      // ready for next replay
    }
    g_xs[idx] = __ldg(&x[idx]) * d;
}

// Fused gather1 + W1 + relu + W2:  aggregation in 16-dim INPUT space.
//   agg[c] = xs[c] + sum_neighbors xs[r]
//   o1     = relu(dinv * (agg @ W1) + b1)
//   h2s    = (o1 @ W2) * dinv
// Half-warp per node, lane = input feature (16). 16 nodes per 256-thread block.
__global__ void k_gather1_lin12(const float* __restrict__ W1,
                                const float* __restrict__ b1,
                                const float* __restrict__ W2) {
    __shared__ float sW1[FIN * FMID];
    __shared__ float sW2[FMID * FOUT];
    __shared__ float sb1[FMID];
    __shared__ float sagg[16][FIN];
    __shared__ float so1[16][FMID];
    for (int t = threadIdx.x; t < FIN * FMID; t += blockDim.x) {
        sW1[t] = W1[t];
        sW2[t] = W2[t];
    }
    for (int t = threadIdx.x; t < FMID; t += blockDim.x) sb1[t] = b1[t];
    __syncthreads();

    int w = (blockIdx.x * blockDim.x + threadIdx.x) >> 4;   // node (grid exact)
    int f = threadIdx.x & 15;
    int h = (threadIdx.x >> 4) & 15;        // node slot within block

    const int* adj = &g_psrow[w * CAP];
    int deg = g_degc[w];
    float d = g_dinv[w];

    float acc0 = g_xs[w * FIN + f];         // self-loop
    float acc1 = 0.0f;
    int j = 0;
    for (; j + 8 <= deg; j += 8) {
        int r0 = adj[j],   r1 = adj[j+1], r2 = adj[j+2], r3 = adj[j+3];
        int r4 = adj[j+4], r5 = adj[j+5], r6 = adj[j+6], r7 = adj[j+7];
        float a0 = __ldg(&g_xs[r0 * FIN + f]);
        float a1 = __ldg(&g_xs[r1 * FIN + f]);
        float a2 = __ldg(&g_xs[r2 * FIN + f]);
        float a3 = __ldg(&g_xs[r3 * FIN + f]);
        float a4 = __ldg(&g_xs[r4 * FIN + f]);
        float a5 = __ldg(&g_xs[r5 * FIN + f]);
        float a6 = __ldg(&g_xs[r6 * FIN + f]);
        float a7 = __ldg(&g_xs[r7 * FIN + f]);
        acc0 += (a0 + a1) + (a2 + a3);
        acc1 += (a4 + a5) + (a6 + a7);
    }
    for (; j < deg; j++)
        acc0 += __ldg(&g_xs[adj[j] * FIN + f]);
    float acc = acc0 + acc1;

    int sn = g_spill_n;                     // 0 for this input; correctness path
    for (int i = 0; i < sn; i++)
        if (g_spill_c[i] == w)
            acc += __ldg(&g_xs[g_spill_r[i] * FIN + f]);

    sagg[h][f] = acc;
    __syncthreads();

    // mid = agg @ W1 (each thread computes 2 of the 32 outputs for its node)
    {
        float m0 = 0.0f, m1 = 0.0f;
        #pragma unroll
        for (int k = 0; k < FIN; k++) {
            float a = sagg[h][k];
            m0 = fmaf(a, sW1[k * FMID + f],      m0);
            m1 = fmaf(a, sW1[k * FMID + f + 16], m1);
        }
        so1[h][f]      = fmaxf(fmaf(m0, d, sb1[f]),      0.0f);
        so1[h][f + 16] = fmaxf(fmaf(m1, d, sb1[f + 16]), 0.0f);
    }
    __syncthreads();

    // h2s = (o1 @ W2) * dinv
    {
        float s = 0.0f;
        #pragma unroll
        for (int k = 0; k < FMID; k++)
            s = fmaf(so1[h][k], sW2[k * FOUT + f], s);
        g_h2s[w * FOUT + f] = s * d;
    }
}

// Fused gather2 + final. Half-warp per node, lane = feature (16). (R10 layout)
__global__ void k_gather2_final(const float* __restrict__ fcW,
                                const float* __restrict__ fcb,
                                const float* __restrict__ b2,
                                float* __restrict__ out) {
    int h = (blockIdx.x * blockDim.x + threadIdx.x) >> 4;
    if (h >= N_NODES) return;
    int f = threadIdx.x & 15;

    const int* adj = &g_psrow[h * CAP];
    int deg = g_degc[h];
    float acc0 = __ldg(&g_h2s[h * FOUT + f]);   // self-loop
    float acc1 = 0.0f;
    int j = 0;
    for (; j + 8 <= deg; j += 8) {
        int r0 = adj[j],   r1 = adj[j+1], r2 = adj[j+2], r3 = adj[j+3];
        int r4 = adj[j+4], r5 = adj[j+5], r6 = adj[j+6], r7 = adj[j+7];
        float a0 = __ldg(&g_h2s[r0 * FOUT + f]);
        float a1 = __ldg(&g_h2s[r1 * FOUT + f]);
        float a2 = __ldg(&g_h2s[r2 * FOUT + f]);
        float a3 = __ldg(&g_h2s[r3 * FOUT + f]);
        float a4 = __ldg(&g_h2s[r4 * FOUT + f]);
        float a5 = __ldg(&g_h2s[r5 * FOUT + f]);
        float a6 = __ldg(&g_h2s[r6 * FOUT + f]);
        float a7 = __ldg(&g_h2s[r7 * FOUT + f]);
        acc0 += (a0 + a1) + (a2 + a3);
        acc1 += (a4 + a5) + (a6 + a7);
    }
    for (; j < deg; j++)
        acc0 += __ldg(&g_h2s[adj[j] * FOUT + f]);
    float acc = acc0 + acc1;

    int sn = g_spill_n;
    for (int i = 0; i < sn; i++)
        if (g_spill_c[i] == h)
            acc += __ldg(&g_h2s[g_spill_r[i] * FOUT + f]);

    float d = g_dinv[h];
    float v = fmaxf(fmaf(acc, d, __ldg(&b2[f])), 0.0f) * __ldg(&fcW[f]);
    #pragma unroll
    for (int s = 8; s > 0; s >>= 1)
        v += __shfl_xor_sync(0xffffffffu, v, s, 16);
    if (f == 0) out[h] = v + __ldg(&fcb[0]);
}

// ---------------- launch ----------------
extern "C" void kernel_launch(void* const* d_in, const int* in_sizes, int n_in,
                              void* d_out, int out_size) {
    const void*  edge = d_in[0];
    const float* x    = (const float*)d_in[1];
    const float* W1   = (const float*)d_in[2];
    const float* b1   = (const float*)d_in[3];
    const float* W2   = (const float*)d_in[4];
    const float* b2   = (const float*)d_in[5];
    const float* fcW  = (const float*)d_in[6];
    const float* fcb  = (const float*)d_in[7];
    float* out = (float*)d_out;

    const int E = in_sizes[0] / 2;
    const int T = 256;

    k_build         <<<(E / 4 + T - 1) / T, T>>>((const unsigned int*)edge, edge, E);
    k_scale         <<<(N_NODES * FIN + T - 1) / T, T>>>(x);
    k_gather1_lin12 <<<(N_NODES * FIN + T - 1) / T, T>>>(W1, b1, W2);
    k_gather2_final <<<(N_NODES * FOUT + T - 1) / T, T>>>(fcW, fcb, b2, out);
}

// round 13
// speedup vs baseline: 1.3337x; 1.0727x over previous
#include <cuda_runtime.h>

#define N_NODES 100000
#define E_EDGES 1600000
#define FIN  16
#define FMID 32
#define FOUT 16
#define CAP  64                            // padded per-node capacity (mean deg 16)

// ---------------- device scratch ----------------
__device__ int   g_cnt[N_NODES];           // arrival counter / degree (0 at replay start)
__device__ int   g_degc[N_NODES];          // min(deg, CAP) snapshot for gathers
__device__ float g_dinv[N_NODES];
__device__ int   g_psrow[N_NODES * CAP];   // padded adjacency (rows by target)
__device__ int   g_spill_r[E_EDGES];       // overflow edges (rank >= CAP)
__device__ int   g_spill_c[E_EDGES];
__device__ int   g_spill_cursor;           // 0 at replay start
__device__ int   g_spill_n;                // snapshot for gathers
__device__ float g_xs [N_NODES * FIN];     // x * dinv  (layer-1 gather source, 64B rows)
__device__ float g_h2s[N_NODES * FOUT];    // (relu(o1) @ W2) * dinv

// ---------------- kernels ----------------

// Fused dtype-detect + padded-CSR build. One atomic per edge gives both the
// degree histogram AND the final storage slot. Vectorized edge reads.
__global__ void k_build(const unsigned int* __restrict__ words,
                        const void* __restrict__ edge_raw, int E) {
    __shared__ unsigned int s_or;
    if (threadIdx.x == 0) s_or = 0u;
    __syncthreads();
    unsigned int acc = words[2 * threadIdx.x + 1] | words[2 * (threadIdx.x + 256) + 1];
    #pragma unroll
    for (int s = 16; s > 0; s >>= 1)
        acc |= __shfl_xor_sync(0xffffffffu, acc, s);
    if ((threadIdx.x & 31) == 0) atomicOr(&s_or, acc);
    __syncthreads();
    const int is64 = (s_or == 0u) ? 1 : 0;

    int base = (blockIdx.x * blockDim.x + threadIdx.x) * 4;
    if (base >= E) return;
    int n = min(4, E - base);

    int r[4], c[4];
    if (n == 4) {
        if (is64) {       // 4 edges = 2x16B per half (base is 4-aligned)
            const longlong2* p2 = (const longlong2*)edge_raw;
            longlong2 ra = __ldg(&p2[(base >> 1)]);
            longlong2 rb = __ldg(&p2[(base >> 1) + 1]);
            longlong2 ca = __ldg(&p2[((E + base) >> 1)]);
            longlong2 cb = __ldg(&p2[((E + base) >> 1) + 1]);
            r[0] = (int)ra.x; r[1] = (int)ra.y; r[2] = (int)rb.x; r[3] = (int)rb.y;
            c[0] = (int)ca.x; c[1] = (int)ca.y; c[2] = (int)cb.x; c[3] = (int)cb.y;
        } else {
            const int4* p4 = (const int4*)edge_raw;
            int4 rv = __ldg(&p4[base >> 2]);
            int4 cv = __ldg(&p4[(E + base) >> 2]);     // E multiple of 4 here
            r[0] = rv.x; r[1] = rv.y; r[2] = rv.z; r[3] = rv.w;
            c[0] = cv.x; c[1] = cv.y; c[2] = cv.z; c[3] = cv.w;
        }
    } else {
        #pragma unroll
        for (int k = 0; k < 4; k++) if (k < n) {
            if (is64) {
                const long long* p = (const long long*)edge_raw;
                r[k] = (int)p[base + k];  c[k] = (int)p[E + base + k];
            } else {
                const int* p = (const int*)edge_raw;
                r[k] = p[base + k];       c[k] = p[E + base + k];
            }
        }
    }
    int rank[4];
    #pragma unroll
    for (int k = 0; k < 4; k++) if (k < n)
        rank[k] = atomicAdd(&g_cnt[c[k]], 1);
    #pragma unroll
    for (int k = 0; k < 4; k++) if (k < n) {
        if (rank[k] < CAP) {
            g_psrow[c[k] * CAP + rank[k]] = r[k];
        } else {                                   // correctness fallback (empty here)
            int s = atomicAdd(&g_spill_cursor, 1);
            g_spill_c[s] = c[k];
            g_spill_r[s] = r[k];
        }
    }
}

// xs = x * dinv ; degree snapshot + counter reset. 16 lanes per node.
__global__ void k_scale(const float* __restrict__ x) {
    int idx = blockIdx.x * blockDim.x + threadIdx.x;
    if (idx == 0) {
        g_spill_n = g_spill_cursor;
        g_spill_cursor = 0;
    }
    if (idx >= N_NODES * FIN) return;
    int i = idx >> 4;
    int f = idx & 15;
    int deg = g_cnt[i];                     // all 16 lanes read before lane-0 resets
    float d = rsqrtf((float)(deg + 1));     // +1 self-loop
    __syncwarp();
    if (f == 0) {
        g_dinv[i] = d;
        g_degc[i] = min(deg, CAP);
        g_cnt[i]  = 0;                      // ready for next replay
    }
    g_xs[idx] = __ldg(&x[idx]) * d;
}

// Fused gather1 + W1 + relu + W2 (aggregation in 16-dim input space).
// Half-warp per node, lane = input feature. int4 index loads, 8 gathers in flight.
__global__ void k_gather1_lin12(const float* __restrict__ W1,
                                const float* __restrict__ b1,
                                const float* __restrict__ W2) {
    __shared__ float sW1[FIN * FMID];
    __shared__ float sW2[FMID * FOUT];
    __shared__ float sb1[FMID];
    __shared__ float sagg[16][FIN];
    __shared__ float so1[16][FMID];
    for (int t = threadIdx.x; t < FIN * FMID; t += blockDim.x) {
        sW1[t] = W1[t];
        sW2[t] = W2[t];
    }
    for (int t = threadIdx.x; t < FMID; t += blockDim.x) sb1[t] = b1[t];
    __syncthreads();

    int w = (blockIdx.x * blockDim.x + threadIdx.x) >> 4;   // node (grid exact)
    int f = threadIdx.x & 15;
    int h = (threadIdx.x >> 4) & 15;

    const int4* adj4 = (const int4*)&g_psrow[w * CAP];
    int deg = g_degc[w];
    float d = g_dinv[w];

    float acc0 = g_xs[w * FIN + f];         // self-loop
    float acc1 = 0.0f;
    int j = 0;
    for (; j + 8 <= deg; j += 8) {
        int4 ia = __ldg(&adj4[j >> 2]);
        int4 ib = __ldg(&adj4[(j >> 2) + 1]);
        float a0 = __ldg(&g_xs[ia.x * FIN + f]);
        float a1 = __ldg(&g_xs[ia.y * FIN + f]);
        float a2 = __ldg(&g_xs[ia.z * FIN + f]);
        float a3 = __ldg(&g_xs[ia.w * FIN + f]);
        float a4 = __ldg(&g_xs[ib.x * FIN + f]);
        float a5 = __ldg(&g_xs[ib.y * FIN + f]);
        float a6 = __ldg(&g_xs[ib.z * FIN + f]);
        float a7 = __ldg(&g_xs[ib.w * FIN + f]);
        acc0 += (a0 + a1) + (a2 + a3);
        acc1 += (a4 + a5) + (a6 + a7);
    }
    for (; j < deg; j++)
        acc0 += __ldg(&g_xs[g_psrow[w * CAP + j] * FIN + f]);
    float acc = acc0 + acc1;

    int sn = g_spill_n;                     // 0 for this input; correctness path
    for (int i = 0; i < sn; i++)
        if (g_spill_c[i] == w)
            acc += __ldg(&g_xs[g_spill_r[i] * FIN + f]);

    sagg[h][f] = acc;
    __syncthreads();

    {
        float m0 = 0.0f, m1 = 0.0f;
        #pragma unroll
        for (int k = 0; k < FIN; k++) {
            float a = sagg[h][k];
            m0 = fmaf(a, sW1[k * FMID + f],      m0);
            m1 = fmaf(a, sW1[k * FMID + f + 16], m1);
        }
        so1[h][f]      = fmaxf(fmaf(m0, d, sb1[f]),      0.0f);
        so1[h][f + 16] = fmaxf(fmaf(m1, d, sb1[f + 16]), 0.0f);
    }
    __syncthreads();

    {
        float s = 0.0f;
        #pragma unroll
        for (int k = 0; k < FMID; k++)
            s = fmaf(so1[h][k], sW2[k * FOUT + f], s);
        g_h2s[w * FOUT + f] = s * d;
    }
}

// Fused gather2 + final. Half-warp per node, lane = feature.
// int4 index loads, 8 gathers in flight.
__global__ void k_gather2_final(const float* __restrict__ fcW,
                                const float* __restrict__ fcb,
                                const float* __restrict__ b2,
                                float* __restrict__ out) {
    int h = (blockIdx.x * blockDim.x + threadIdx.x) >> 4;
    if (h >= N_NODES) return;
    int f = threadIdx.x & 15;

    const int4* adj4 = (const int4*)&g_psrow[h * CAP];
    int deg = g_degc[h];
    float acc0 = __ldg(&g_h2s[h * FOUT + f]);   // self-loop
    float acc1 = 0.0f;
    int j = 0;
    for (; j + 8 <= deg; j += 8) {
        int4 ia = __ldg(&adj4[j >> 2]);
        int4 ib = __ldg(&adj4[(j >> 2) + 1]);
        float a0 = __ldg(&g_h2s[ia.x * FOUT + f]);
        float a1 = __ldg(&g_h2s[ia.y * FOUT + f]);
        float a2 = __ldg(&g_h2s[ia.z * FOUT + f]);
        float a3 = __ldg(&g_h2s[ia.w * FOUT + f]);
        float a4 = __ldg(&g_h2s[ib.x * FOUT + f]);
        float a5 = __ldg(&g_h2s[ib.y * FOUT + f]);
        float a6 = __ldg(&g_h2s[ib.z * FOUT + f]);
        float a7 = __ldg(&g_h2s[ib.w * FOUT + f]);
        acc0 += (a0 + a1) + (a2 + a3);
        acc1 += (a4 + a5) + (a6 + a7);
    }
    for (; j < deg; j++)
        acc0 += __ldg(&g_h2s[g_psrow[h * CAP + j] * FOUT + f]);
    float acc = acc0 + acc1;

    int sn = g_spill_n;
    for (int i = 0; i < sn; i++)
        if (g_spill_c[i] == h)
            acc += __ldg(&g_h2s[g_spill_r[i] * FOUT + f]);

    float d = g_dinv[h];
    float v = fmaxf(fmaf(acc, d, __ldg(&b2[f])), 0.0f) * __ldg(&fcW[f]);
    #pragma unroll
    for (int s = 8; s > 0; s >>= 1)
        v += __shfl_xor_sync(0xffffffffu, v, s, 16);
    if (f == 0) out[h] = v + __ldg(&fcb[0]);
}

// ---------------- launch ----------------
extern "C" void kernel_launch(void* const* d_in, const int* in_sizes, int n_in,
                              void* d_out, int out_size) {
    const void*  edge = d_in[0];
    const float* x    = (const float*)d_in[1];
    const float* W1   = (const float*)d_in[2];
    const float* b1   = (const float*)d_in[3];
    const float* W2   = (const float*)d_in[4];
    const float* b2   = (const float*)d_in[5];
    const float* fcW  = (const float*)d_in[6];
    const float* fcb  = (const float*)d_in[7];
    float* out = (float*)d_out;

    const int E = in_sizes[0] / 2;
    const int T = 256;

    k_build         <<<(E / 4 + T - 1) / T, T>>>((const unsigned int*)edge, edge, E);
    k_scale         <<<(N_NODES * FIN + T - 1) / T, T>>>(x);
    k_gather1_lin12 <<<(N_NODES * FIN + T - 1) / T, T>>>(W1, b1, W2);
    k_gather2_final <<<(N_NODES * FOUT + T - 1) / T, T>>>(fcW, fcb, b2, out);
}